// round 10
// baseline (speedup 1.0000x reference)
#include <cuda_runtime.h>
#include <cuda_fp16.h>
#include <math.h>

#define N_NODES 200000
#define N_EDGES 12800000
#define ALPHA   0.1f
#define DT      0.01f
#define EPS_    1e-9f
#define DIFF_   10.0f
#define HARD    1.57079632679489662f

#define EPT        16                      // edges per thread
#define N_THREADS  (N_EDGES / EPT)         // 800,000 = 3125 * 256 exactly

// Scratch (device globals — no allocation allowed)
__device__ __half2 g_uv[N_NODES];   // pre-rotated (u,v) = e^{-i phi}(x+iy)
__device__ float2  g_cs[N_NODES];   // (cos phi, sin phi) cached for finalize
__device__ float2  g_sum[N_NODES];  // per-node gathered sum, atomic-accumulated

__device__ __forceinline__ void pdl_wait()    { asm volatile("griddepcontrol.wait;" ::: "memory"); }
__device__ __forceinline__ void pdl_trigger() { asm volatile("griddepcontrol.launch_dependents;" ::: "memory"); }

// Vector red: one instruction adds (u,v) to a float2 in gmem
__device__ __forceinline__ void red_add_v2(float2* addr, float u, float v)
{
    asm volatile("red.global.add.v2.f32 [%0], {%1, %2};"
                 :: "l"(addr), "f"(u), "f"(v) : "memory");
}

// ---------------------------------------------------------------------------
// K1: per-node prep. Trigger FIRST so the edge grid launches concurrently.
// Computes uv (half2) + caches (c,s) for finalize + zeroes g_sum.
// ---------------------------------------------------------------------------
__global__ void __launch_bounds__(256) uv_kernel(
    const float* __restrict__ phase,
    const float* __restrict__ xy)
{
    pdl_trigger();
    int i = blockIdx.x * blockDim.x + threadIdx.x;
    if (i < N_NODES) {
        float s, c;
        __sincosf(phase[i], &s, &c);
        float2 p = ((const float2*)xy)[i];
        g_uv[i]  = __floats2half2_rn(fmaf(c, p.x, s * p.y), fmaf(c, p.y, -s * p.x));
        g_cs[i]  = make_float2(c, s);
        g_sum[i] = make_float2(0.0f, 0.0f);
    }
}

// ---------------------------------------------------------------------------
// K2: fused edge pass. 16 edges/thread: coalesced int4 streams (issued before
// the PDL wait -> overlap with uv), 16-deep gather MLP, register run-length
// scan, warp shfl segmented merge, ONE vector red per run flush.
// ---------------------------------------------------------------------------
__global__ void __launch_bounds__(256) edge_kernel(
    const int* __restrict__ src,
    const int* __restrict__ dst)
{
    pdl_trigger();
    int t = blockIdx.x * blockDim.x + threadIdx.x;   // grid is exactly N_THREADS
    int lane = threadIdx.x & 31;
    int base = t * EPT;

    // Independent streaming loads (overlap with uv kernel via PDL)
    int4 s0 = __ldcs((const int4*)(src + base) + 0);
    int4 s1 = __ldcs((const int4*)(src + base) + 1);
    int4 s2 = __ldcs((const int4*)(src + base) + 2);
    int4 s3 = __ldcs((const int4*)(src + base) + 3);
    int4 d0 = __ldcs((const int4*)(dst + base) + 0);
    int4 d1 = __ldcs((const int4*)(dst + base) + 1);
    int4 d2 = __ldcs((const int4*)(dst + base) + 2);
    int4 d3 = __ldcs((const int4*)(dst + base) + 3);

    pdl_wait();   // g_uv / g_sum now visible

    int k[EPT] = { s0.x, s0.y, s0.z, s0.w,  s1.x, s1.y, s1.z, s1.w,
                   s2.x, s2.y, s2.z, s2.w,  s3.x, s3.y, s3.z, s3.w };
    int di[EPT] = { d0.x, d0.y, d0.z, d0.w,  d1.x, d1.y, d1.z, d1.w,
                    d2.x, d2.y, d2.z, d2.w,  d3.x, d3.y, d3.z, d3.w };

    __half2 h[EPT];
    #pragma unroll
    for (int e = 0; e < EPT; e++) h[e] = __ldg(&g_uv[di[e]]);

    // Run-length scan over sorted keys; interior runs flush immediately
    int   cur = k[0];
    float2 f0 = __half22float2(h[0]);
    float U = f0.x, V = f0.y;
    #pragma unroll
    for (int e = 1; e < EPT; e++) {
        float2 f = __half22float2(h[e]);
        if (k[e] != cur) {
            red_add_v2(&g_sum[cur], U, V);
            cur = k[e];
            U = f.x; V = f.y;
        } else {
            U += f.x; V += f.y;
        }
    }

    // Warp segmented merge of pending runs (keys nondecreasing across lanes)
    #pragma unroll
    for (int o = 1; o < 32; o <<= 1) {
        int   pk = __shfl_up_sync(0xffffffffu, cur, o);
        float pU = __shfl_up_sync(0xffffffffu, U, o);
        float pV = __shfl_up_sync(0xffffffffu, V, o);
        if (lane >= o && pk == cur) { U += pU; V += pV; }
    }
    int nk = __shfl_down_sync(0xffffffffu, cur, 1);
    if (lane == 31 || nk != cur) {
        red_add_v2(&g_sum[cur], U, V);
    }
}

// ---------------------------------------------------------------------------
// K3: thread-per-node finalize. g_sum-independent input streams issued before
// the PDL wait; after the wait only two coalesced loads (g_sum, g_cs) — the
// sincos is gone (cached by K1).
// ---------------------------------------------------------------------------
__global__ void __launch_bounds__(256) finalize_kernel(
    const float* __restrict__ phase,
    const float* __restrict__ xy,
    const float* __restrict__ xy_dot_old,
    const float* __restrict__ w,
    const float* __restrict__ amp,
    const float* __restrict__ ha,
    float*       __restrict__ out)
{
    int i = blockIdx.x * blockDim.x + threadIdx.x;
    if (i >= N_NODES) { pdl_wait(); return; }

    float2 p  = ((const float2*)xy)[i];
    float2 pd = ((const float2*)xy_dot_old)[i];
    float  wi = w[i];
    float  am = amp[i];
    float  hi = ha[i];

    pdl_wait();   // edge atomics + K1's g_cs (transitively) visible
    float2 sv = g_sum[i];
    float2 cs = g_cs[i];

    float sum_x = fmaf(cs.x, sv.x, -cs.y * sv.y);
    float sum_y = fmaf(cs.y, sv.x,  cs.x * sv.y);

    float r2   = fmaf(p.x, p.x, p.y * p.y);
    float a    = ALPHA * (1.0f - r2 * r2);
    float zeta = 1.0f - hi * ((pd.x + EPS_) / (fabsf(pd.x) + EPS_));
    float b    = wi / (zeta + EPS_);

    float kx = fmaf(a, p.x, -b * p.y);
    float ky = fmaf(b, p.x,  a * p.y);

    float x_dot = fminf(fmaxf(kx + sum_x, pd.x - DIFF_), pd.x + DIFF_);
    float y_dot = fminf(fmaxf(ky + sum_y, pd.y - DIFF_), pd.y + DIFF_);

    float xn = fmaf(x_dot, DT, p.x);
    float yn = fmaf(y_dot, DT, p.y);
    float ang = fminf(fmaxf(am * yn, -HARD), HARD);

    out[i] = ang;                                              // angles
    ((float2*)(out + N_NODES))[i]     = make_float2(xn, yn);   // xy_new
    ((float2*)(out + 3 * N_NODES))[i] = p;                     // xy_dot_old_new = xy
}

extern "C" void kernel_launch(void* const* d_in, const int* in_sizes, int n_in,
                              void* d_out, int out_size)
{
    const float* xy         = (const float*)d_in[0];
    const float* xy_dot_old = (const float*)d_in[1];
    const float* phase      = (const float*)d_in[2];
    const float* w          = (const float*)d_in[3];
    const float* amplitudes = (const float*)d_in[4];
    const float* ha         = (const float*)d_in[5];
    const int*   edge_src   = (const int*)d_in[6];
    const int*   edge_dst   = (const int*)d_in[7];
    float* out = (float*)d_out;

    int nb_nodes = (N_NODES + 255) / 256;
    int nb_edge  = N_THREADS / 256;          // 3125, exact

    cudaLaunchAttribute pdl_attr[1];
    pdl_attr[0].id = cudaLaunchAttributeProgrammaticStreamSerialization;
    pdl_attr[0].val.programmaticStreamSerializationAllowed = 1;

    uv_kernel<<<nb_nodes, 256>>>(phase, xy);

    {
        cudaLaunchConfig_t cfg = {};
        cfg.gridDim  = dim3(nb_edge);
        cfg.blockDim = dim3(256);
        cfg.stream   = 0;
        cfg.attrs    = pdl_attr;
        cfg.numAttrs = 1;
        cudaLaunchKernelEx(&cfg, edge_kernel, edge_src, edge_dst);
    }
    {
        cudaLaunchConfig_t cfg = {};
        cfg.gridDim  = dim3(nb_nodes);
        cfg.blockDim = dim3(256);
        cfg.stream   = 0;
        cfg.attrs    = pdl_attr;
        cfg.numAttrs = 1;
        cudaLaunchKernelEx(&cfg, finalize_kernel, phase, xy, xy_dot_old, w,
                           amplitudes, ha, out);
    }
}

// round 11
// speedup vs baseline: 1.0398x; 1.0398x over previous
#include <cuda_runtime.h>
#include <cuda_fp16.h>
#include <math.h>

#define N_NODES 200000
#define N_EDGES 12800000
#define ALPHA   0.1f
#define DT      0.01f
#define EPS_    1e-9f
#define DIFF_   10.0f
#define HARD    1.57079632679489662f

#define EPT        16                      // edges per thread
#define N_THREADS  (N_EDGES / EPT)         // 800,000 = 3125 * 256 exactly

// Scratch (device globals — no allocation allowed)
__device__ __half2 g_uv[N_NODES];   // pre-rotated (u,v) = e^{-i phi}(x+iy)
__device__ float2  g_cs[N_NODES];   // (cos phi, sin phi) cached for finalize
__device__ float2  g_sum[N_NODES];  // per-node gathered sum, atomic-accumulated

__device__ __forceinline__ void pdl_wait()    { asm volatile("griddepcontrol.wait;" ::: "memory"); }
__device__ __forceinline__ void pdl_trigger() { asm volatile("griddepcontrol.launch_dependents;" ::: "memory"); }

// ---------------------------------------------------------------------------
// K1: per-node prep. Trigger FIRST so the edge grid launches concurrently.
// Computes uv (half2) + caches (c,s) for finalize + zeroes g_sum.
// ---------------------------------------------------------------------------
__global__ void __launch_bounds__(256) uv_kernel(
    const float* __restrict__ phase,
    const float* __restrict__ xy)
{
    pdl_trigger();
    int i = blockIdx.x * blockDim.x + threadIdx.x;
    if (i < N_NODES) {
        float s, c;
        __sincosf(phase[i], &s, &c);
        float2 p = ((const float2*)xy)[i];
        g_uv[i]  = __floats2half2_rn(fmaf(c, p.x, s * p.y), fmaf(c, p.y, -s * p.x));
        g_cs[i]  = make_float2(c, s);
        g_sum[i] = make_float2(0.0f, 0.0f);
    }
}

// ---------------------------------------------------------------------------
// K2: fused edge pass. 16 edges/thread: coalesced int4 streams (issued before
// the PDL wait -> overlap with uv), 16-deep gather MLP, register run-length
// scan, warp shfl segmented merge, scalar atomicAdd per run flush (the
// scalar REDG path is the fast atomic class on this part — v2 red regressed).
// ---------------------------------------------------------------------------
__global__ void __launch_bounds__(256) edge_kernel(
    const int* __restrict__ src,
    const int* __restrict__ dst)
{
    pdl_trigger();
    int t = blockIdx.x * blockDim.x + threadIdx.x;   // grid is exactly N_THREADS
    int lane = threadIdx.x & 31;
    int base = t * EPT;

    // Independent streaming loads (overlap with uv kernel via PDL)
    int4 s0 = __ldcs((const int4*)(src + base) + 0);
    int4 s1 = __ldcs((const int4*)(src + base) + 1);
    int4 s2 = __ldcs((const int4*)(src + base) + 2);
    int4 s3 = __ldcs((const int4*)(src + base) + 3);
    int4 d0 = __ldcs((const int4*)(dst + base) + 0);
    int4 d1 = __ldcs((const int4*)(dst + base) + 1);
    int4 d2 = __ldcs((const int4*)(dst + base) + 2);
    int4 d3 = __ldcs((const int4*)(dst + base) + 3);

    pdl_wait();   // g_uv / g_sum now visible

    int k[EPT] = { s0.x, s0.y, s0.z, s0.w,  s1.x, s1.y, s1.z, s1.w,
                   s2.x, s2.y, s2.z, s2.w,  s3.x, s3.y, s3.z, s3.w };
    int di[EPT] = { d0.x, d0.y, d0.z, d0.w,  d1.x, d1.y, d1.z, d1.w,
                    d2.x, d2.y, d2.z, d2.w,  d3.x, d3.y, d3.z, d3.w };

    __half2 h[EPT];
    #pragma unroll
    for (int e = 0; e < EPT; e++) h[e] = __ldg(&g_uv[di[e]]);

    // Run-length scan over sorted keys; interior runs flush immediately
    int   cur = k[0];
    float2 f0 = __half22float2(h[0]);
    float U = f0.x, V = f0.y;
    #pragma unroll
    for (int e = 1; e < EPT; e++) {
        float2 f = __half22float2(h[e]);
        if (k[e] != cur) {
            atomicAdd(&g_sum[cur].x, U);
            atomicAdd(&g_sum[cur].y, V);
            cur = k[e];
            U = f.x; V = f.y;
        } else {
            U += f.x; V += f.y;
        }
    }

    // Warp segmented merge of pending runs (keys nondecreasing across lanes)
    #pragma unroll
    for (int o = 1; o < 32; o <<= 1) {
        int   pk = __shfl_up_sync(0xffffffffu, cur, o);
        float pU = __shfl_up_sync(0xffffffffu, U, o);
        float pV = __shfl_up_sync(0xffffffffu, V, o);
        if (lane >= o && pk == cur) { U += pU; V += pV; }
    }
    int nk = __shfl_down_sync(0xffffffffu, cur, 1);
    if (lane == 31 || nk != cur) {
        atomicAdd(&g_sum[cur].x, U);
        atomicAdd(&g_sum[cur].y, V);
    }
}

// ---------------------------------------------------------------------------
// K3: thread-per-node finalize. g_sum-independent input streams issued before
// the PDL wait; after the wait only two coalesced loads (g_sum, g_cs) — the
// sincos is gone (cached by K1).
// ---------------------------------------------------------------------------
__global__ void __launch_bounds__(256) finalize_kernel(
    const float* __restrict__ phase,
    const float* __restrict__ xy,
    const float* __restrict__ xy_dot_old,
    const float* __restrict__ w,
    const float* __restrict__ amp,
    const float* __restrict__ ha,
    float*       __restrict__ out)
{
    int i = blockIdx.x * blockDim.x + threadIdx.x;
    if (i >= N_NODES) { pdl_wait(); return; }

    float2 p  = ((const float2*)xy)[i];
    float2 pd = ((const float2*)xy_dot_old)[i];
    float  wi = w[i];
    float  am = amp[i];
    float  hi = ha[i];

    pdl_wait();   // edge atomics + K1's g_cs (transitively) visible
    float2 sv = g_sum[i];
    float2 cs = g_cs[i];

    float sum_x = fmaf(cs.x, sv.x, -cs.y * sv.y);
    float sum_y = fmaf(cs.y, sv.x,  cs.x * sv.y);

    float r2   = fmaf(p.x, p.x, p.y * p.y);
    float a    = ALPHA * (1.0f - r2 * r2);
    float zeta = 1.0f - hi * ((pd.x + EPS_) / (fabsf(pd.x) + EPS_));
    float b    = wi / (zeta + EPS_);

    float kx = fmaf(a, p.x, -b * p.y);
    float ky = fmaf(b, p.x,  a * p.y);

    float x_dot = fminf(fmaxf(kx + sum_x, pd.x - DIFF_), pd.x + DIFF_);
    float y_dot = fminf(fmaxf(ky + sum_y, pd.y - DIFF_), pd.y + DIFF_);

    float xn = fmaf(x_dot, DT, p.x);
    float yn = fmaf(y_dot, DT, p.y);
    float ang = fminf(fmaxf(am * yn, -HARD), HARD);

    out[i] = ang;                                              // angles
    ((float2*)(out + N_NODES))[i]     = make_float2(xn, yn);   // xy_new
    ((float2*)(out + 3 * N_NODES))[i] = p;                     // xy_dot_old_new = xy
}

extern "C" void kernel_launch(void* const* d_in, const int* in_sizes, int n_in,
                              void* d_out, int out_size)
{
    const float* xy         = (const float*)d_in[0];
    const float* xy_dot_old = (const float*)d_in[1];
    const float* phase      = (const float*)d_in[2];
    const float* w          = (const float*)d_in[3];
    const float* amplitudes = (const float*)d_in[4];
    const float* ha         = (const float*)d_in[5];
    const int*   edge_src   = (const int*)d_in[6];
    const int*   edge_dst   = (const int*)d_in[7];
    float* out = (float*)d_out;

    int nb_nodes = (N_NODES + 255) / 256;
    int nb_edge  = N_THREADS / 256;          // 3125, exact

    cudaLaunchAttribute pdl_attr[1];
    pdl_attr[0].id = cudaLaunchAttributeProgrammaticStreamSerialization;
    pdl_attr[0].val.programmaticStreamSerializationAllowed = 1;

    uv_kernel<<<nb_nodes, 256>>>(phase, xy);

    {
        cudaLaunchConfig_t cfg = {};
        cfg.gridDim  = dim3(nb_edge);
        cfg.blockDim = dim3(256);
        cfg.stream   = 0;
        cfg.attrs    = pdl_attr;
        cfg.numAttrs = 1;
        cudaLaunchKernelEx(&cfg, edge_kernel, edge_src, edge_dst);
    }
    {
        cudaLaunchConfig_t cfg = {};
        cfg.gridDim  = dim3(nb_nodes);
        cfg.blockDim = dim3(256);
        cfg.stream   = 0;
        cfg.attrs    = pdl_attr;
        cfg.numAttrs = 1;
        cudaLaunchKernelEx(&cfg, finalize_kernel, phase, xy, xy_dot_old, w,
                           amplitudes, ha, out);
    }
}